// round 8
// baseline (speedup 1.0000x reference)
#include <cuda_runtime.h>
#include <cuda_fp16.h>
#include <math.h>

#define NN 50000
#define EE 800000
#define NG4 (4 * NN)
#define EG4 (4 * EE)

// ---------------- scratch (static device globals; no runtime alloc) ----------------
__device__ int    g_CNT[NG4];
__device__ int    g_ROWPTR[NG4 + 1];
__device__ int    g_CUR[NG4];
__device__ int    g_ESRC[EG4];
__device__ int    g_EDST[EG4];
__device__ float  g_EVAL[EG4];
__device__ int    g_EPD[EE];                      // perm[dst] for adj edges
__device__ __half g_Xh[(size_t)NN * 64];          // feat@W_enc + b_enc (fp16 gather table)
__device__ __half g_Hh0[(size_t)NN * 64];         // relu(h)   fp16
__device__ __half g_Hh1[(size_t)NN * 64];         // relu(h_g) fp16
__device__ float  g_S[(size_t)NN * 64];           // spmm(adj, relu_h)
__device__ float  g_MLPIN[(size_t)5 * NN * 64];   // h, h_g, shuf_h, sig_neigh, sig_diff
__device__ float  g_MLPOUT[(size_t)5 * NN * 64];  // z, z_g, shuf_z, g, g_g
__device__ float  g_DEG[3 * NN];                  // [adj | neigh | diff]

// ---------------- tf32 helpers ----------------
__device__ __forceinline__ unsigned cvt_tf32(float x) {
    unsigned u;
    asm("cvt.rna.tf32.f32 %0, %1;" : "=r"(u) : "f"(x));
    return u;
}
__device__ __forceinline__ void mma8(float* c, const unsigned* a, const unsigned* b) {
    asm("mma.sync.aligned.m16n8k8.row.col.f32.tf32.tf32.f32 "
        "{%0,%1,%2,%3},{%4,%5,%6,%7},{%8,%9},{%0,%1,%2,%3};"
        : "+f"(c[0]), "+f"(c[1]), "+f"(c[2]), "+f"(c[3])
        : "r"(a[0]), "r"(a[1]), "r"(a[2]), "r"(a[3]), "r"(b[0]), "r"(b[1]));
}

#define CP16(sdst, gsrc) \
    asm volatile("cp.async.ca.shared.global [%0], [%1], 16;" ::"r"(sdst), "l"(gsrc))
#define CP_COMMIT() asm volatile("cp.async.commit_group;")
#define CP_WAIT0() asm volatile("cp.async.wait_group 0;" ::: "memory")

// =============================== CSR construction ====================================
__global__ void hist4(const int* __restrict__ sA, const int* __restrict__ sG,
                      const int* __restrict__ sN, const int* __restrict__ sD,
                      int* __restrict__ cnt) {
    int e = blockIdx.x * blockDim.x + threadIdx.x;
    if (e < EE) {
        atomicAdd(&cnt[sA[e]], 1);
        atomicAdd(&cnt[NN + sG[e]], 1);
        atomicAdd(&cnt[2 * NN + sN[e]], 1);
        atomicAdd(&cnt[3 * NN + sD[e]], 1);
    }
}

__global__ void scan_kernel(const int* __restrict__ cnt, int* __restrict__ rowptr,
                            int* __restrict__ cur) {
    __shared__ int part[1024];
    const int T = NG4, C = (T + 1023) / 1024;
    int t = threadIdx.x;
    int lo = t * C, hi = min(T, lo + C);
    int s = 0;
    for (int j = lo; j < hi; j++) s += cnt[j];
    part[t] = s;
    __syncthreads();
    for (int off = 1; off < 1024; off <<= 1) {
        int v = (t >= off) ? part[t - off] : 0;
        __syncthreads();
        part[t] += v;
        __syncthreads();
    }
    int run = part[t] - s;
    for (int j = lo; j < hi; j++) {
        rowptr[j] = run;
        cur[j] = run;
        run += cnt[j];
    }
    if (t == 0) rowptr[T] = EG4;
}

__global__ void scatter4(const int* __restrict__ sA, const int* __restrict__ dA,
                         const float* __restrict__ vA, const int* __restrict__ sG,
                         const int* __restrict__ dG, const float* __restrict__ vG,
                         const int* __restrict__ sN, const int* __restrict__ dN,
                         const float* __restrict__ vN, const int* __restrict__ sD,
                         const int* __restrict__ dD, const float* __restrict__ vD,
                         const int* __restrict__ perm, int* __restrict__ cur,
                         int* __restrict__ esrc, int* __restrict__ edst,
                         float* __restrict__ eval, int* __restrict__ epd) {
    int e = blockIdx.x * blockDim.x + threadIdx.x;
    if (e >= EE) return;
    {
        int ss = sA[e], d = dA[e];
        int p = atomicAdd(&cur[ss], 1);  // p < EE
        esrc[p] = ss;
        edst[p] = d;
        eval[p] = vA[e];
        epd[p] = perm[d];
    }
    {
        int ss = sG[e];
        int p = atomicAdd(&cur[NN + ss], 1);
        esrc[p] = ss;
        edst[p] = dG[e];
        eval[p] = vG[e];
    }
    {
        int ss = sN[e];
        int p = atomicAdd(&cur[2 * NN + ss], 1);
        esrc[p] = ss;
        edst[p] = dN[e];
        eval[p] = vN[e];
    }
    {
        int ss = sD[e];
        int p = atomicAdd(&cur[3 * NN + ss], 1);
        esrc[p] = ss;
        edst[p] = dD[e];
        eval[p] = vD[e];
    }
}

// ======================= segmented-reduction SpMM (sorted edges) =====================
__device__ __forceinline__ void gather8(const __half* base, unsigned off, float* f) {
    uint4 u = *reinterpret_cast<const uint4*>(base + off);
    const __half2* h = reinterpret_cast<const __half2*>(&u);
#pragma unroll
    for (int i = 0; i < 4; i++) {
        float2 a = __half22float2(h[i]);
        f[2 * i] = a.x;
        f[2 * i + 1] = a.y;
    }
}
__device__ __forceinline__ void red4(float* p, float a, float b, float c, float d) {
    asm volatile("red.global.add.v4.f32 [%0], {%1,%2,%3,%4};" ::"l"(p), "f"(a), "f"(b), "f"(c),
                 "f"(d)
                 : "memory");
}

// Edges [esrc,edst,eval) sorted by src. 4 threads/edge (16 cols each).
// Warp-segmented suffix sum over stride-4 lane groups; heads issue atomics.
// Optional weighted-degree output (chunk-0 heads).
__global__ void spmm_seg(const int* __restrict__ esrc, const int* __restrict__ edst,
                         const float* __restrict__ eval, const __half* __restrict__ X,
                         float* __restrict__ out, float* __restrict__ deg, int E) {
    unsigned gid = blockIdx.x * blockDim.x + threadIdx.x;
    unsigned e = gid >> 2;
    int lane = threadIdx.x & 31;
    unsigned c = gid & 3;
    bool valid = e < (unsigned)E;
    int s = -1;
    float v = 0.f;
    float f[16];
#pragma unroll
    for (int i = 0; i < 16; i++) f[i] = 0.f;
    if (valid) {
        s = esrc[e];
        int d = edst[e];
        v = eval[e];
        gather8(X, (unsigned)d * 64 + c * 16, f);
        gather8(X, (unsigned)d * 64 + c * 16 + 8, f + 8);
#pragma unroll
        for (int i = 0; i < 16; i++) f[i] *= v;
    }
    float dg = (c == 0) ? v : 0.f;

#pragma unroll
    for (int off = 4; off <= 16; off <<= 1) {
        int s2 = __shfl_down_sync(0xffffffffu, s, off);
        bool m = (lane + off < 32) && (s2 == s);
#pragma unroll
        for (int i = 0; i < 16; i++) {
            float t = __shfl_down_sync(0xffffffffu, f[i], off);
            if (m) f[i] += t;
        }
        float t = __shfl_down_sync(0xffffffffu, dg, off);
        if (m) dg += t;
    }
    int sprev = __shfl_up_sync(0xffffffffu, s, 4);
    bool head = valid && (lane < 4 || sprev != s);
    if (head) {
        float* p = out + (size_t)s * 64 + c * 16;
#pragma unroll
        for (int i = 0; i < 4; i++)
            red4(p + 4 * i, f[4 * i], f[4 * i + 1], f[4 * i + 2], f[4 * i + 3]);
        if (deg != nullptr && c == 0) atomicAdd(&deg[s], dg);
    }
}

// adj dual: gather X[dst] -> out0 and X[perm[dst]] -> out1, plus adj degree.
__global__ void spmm_seg_dual(const int* __restrict__ esrc, const int* __restrict__ edst,
                              const float* __restrict__ eval, const int* __restrict__ epd,
                              const __half* __restrict__ X, float* __restrict__ out0,
                              float* __restrict__ out1, float* __restrict__ deg, int E) {
    unsigned gid = blockIdx.x * blockDim.x + threadIdx.x;
    unsigned e = gid >> 2;
    int lane = threadIdx.x & 31;
    unsigned c = gid & 3;
    bool valid = e < (unsigned)E;
    int s = -1;
    float v = 0.f;
    float f0[16], f1[16];
#pragma unroll
    for (int i = 0; i < 16; i++) f0[i] = f1[i] = 0.f;
    if (valid) {
        s = esrc[e];
        int d = edst[e];
        int pd = epd[e];
        v = eval[e];
        gather8(X, (unsigned)d * 64 + c * 16, f0);
        gather8(X, (unsigned)d * 64 + c * 16 + 8, f0 + 8);
        gather8(X, (unsigned)pd * 64 + c * 16, f1);
        gather8(X, (unsigned)pd * 64 + c * 16 + 8, f1 + 8);
#pragma unroll
        for (int i = 0; i < 16; i++) {
            f0[i] *= v;
            f1[i] *= v;
        }
    }
    float dg = (c == 0) ? v : 0.f;

#pragma unroll
    for (int off = 4; off <= 16; off <<= 1) {
        int s2 = __shfl_down_sync(0xffffffffu, s, off);
        bool m = (lane + off < 32) && (s2 == s);
#pragma unroll
        for (int i = 0; i < 16; i++) {
            float t0 = __shfl_down_sync(0xffffffffu, f0[i], off);
            float t1 = __shfl_down_sync(0xffffffffu, f1[i], off);
            if (m) {
                f0[i] += t0;
                f1[i] += t1;
            }
        }
        float t = __shfl_down_sync(0xffffffffu, dg, off);
        if (m) dg += t;
    }
    int sprev = __shfl_up_sync(0xffffffffu, s, 4);
    bool head = valid && (lane < 4 || sprev != s);
    if (head) {
        float* p0 = out0 + (size_t)s * 64 + c * 16;
        float* p1 = out1 + (size_t)s * 64 + c * 16;
#pragma unroll
        for (int i = 0; i < 4; i++) {
            red4(p0 + 4 * i, f0[4 * i], f0[4 * i + 1], f0[4 * i + 2], f0[4 * i + 3]);
            red4(p1 + 4 * i, f1[4 * i], f1[4 * i + 1], f1[4 * i + 2], f1[4 * i + 3]);
        }
        if (c == 0) atomicAdd(&deg[s], dg);
    }
}

// ---------------- single-TF32 GEMM ----------------
// BM=128, BN=64, BK=32, 256 threads (8 warps: 4m x 2n).
// EPI 1: C = relu(acc + deg[m]*bias[n])   (fp32 out)
// EPI 2: Ch = half(acc + bias[n])          (fp16 out)
template <int EPI>
__global__ __launch_bounds__(256) void mma_gemm(const float* __restrict__ A,
                                                const float* __restrict__ W,
                                                const float* __restrict__ bias,
                                                const float* __restrict__ deg,
                                                float* __restrict__ C, __half* __restrict__ Ch,
                                                int M, int K, int Nc) {
    __shared__ unsigned As[128][36];
    __shared__ unsigned Bs[32][72];

    const int tid = threadIdx.x, lane = tid & 31, wid = tid >> 5;
    const int bm = blockIdx.y * 128, bn0 = blockIdx.x * 64;
    const int m_base = (wid & 3) * 32, n_base = (wid >> 2) * 32;
    const int lr = lane >> 2, lk = lane & 3;

    float acc[2][4][4];
#pragma unroll
    for (int mi = 0; mi < 2; mi++)
#pragma unroll
        for (int ni = 0; ni < 4; ni++)
#pragma unroll
            for (int i = 0; i < 4; i++) acc[mi][ni][i] = 0.f;

    for (int k0 = 0; k0 < K; k0 += 32) {
#pragma unroll
        for (int p = 0; p < 4; p++) {
            int idx = tid + p * 256;
            int row = idx >> 3, q = idx & 7;
            float4 v = make_float4(0.f, 0.f, 0.f, 0.f);
            if (bm + row < M)
                v = *reinterpret_cast<const float4*>(A + (size_t)(bm + row) * K + k0 + q * 4);
            As[row][q * 4 + 0] = cvt_tf32(v.x);
            As[row][q * 4 + 1] = cvt_tf32(v.y);
            As[row][q * 4 + 2] = cvt_tf32(v.z);
            As[row][q * 4 + 3] = cvt_tf32(v.w);
        }
#pragma unroll
        for (int p = 0; p < 2; p++) {
            int idx = tid + p * 256;
            int kr = idx >> 4, q = idx & 15;
            float4 v = *reinterpret_cast<const float4*>(W + (size_t)(k0 + kr) * Nc + bn0 + q * 4);
            Bs[kr][q * 4 + 0] = cvt_tf32(v.x);
            Bs[kr][q * 4 + 1] = cvt_tf32(v.y);
            Bs[kr][q * 4 + 2] = cvt_tf32(v.z);
            Bs[kr][q * 4 + 3] = cvt_tf32(v.w);
        }
        __syncthreads();

#pragma unroll
        for (int kk = 0; kk < 4; kk++) {
            unsigned a[2][4], b[4][2];
#pragma unroll
            for (int mi = 0; mi < 2; mi++) {
                int r0 = m_base + mi * 16 + lr;
                a[mi][0] = As[r0][kk * 8 + lk];
                a[mi][1] = As[r0 + 8][kk * 8 + lk];
                a[mi][2] = As[r0][kk * 8 + lk + 4];
                a[mi][3] = As[r0 + 8][kk * 8 + lk + 4];
            }
#pragma unroll
            for (int ni = 0; ni < 4; ni++) {
                int cn = n_base + ni * 8 + lr;
                b[ni][0] = Bs[kk * 8 + lk][cn];
                b[ni][1] = Bs[kk * 8 + lk + 4][cn];
            }
#pragma unroll
            for (int mi = 0; mi < 2; mi++)
#pragma unroll
                for (int ni = 0; ni < 4; ni++) mma8(acc[mi][ni], a[mi], b[ni]);
        }
        __syncthreads();
    }

#pragma unroll
    for (int mi = 0; mi < 2; mi++)
#pragma unroll
        for (int ni = 0; ni < 4; ni++) {
#pragma unroll
            for (int hi = 0; hi < 2; hi++) {
                int row = m_base + mi * 16 + lr + hi * 8;
                int col = n_base + ni * 8 + 2 * lk;
                int gm = bm + row, gn = bn0 + col;
                if (gm < M) {
                    float v0 = acc[mi][ni][hi * 2 + 0];
                    float v1 = acc[mi][ni][hi * 2 + 1];
                    if (EPI == 1) {
                        float dg = deg[gm];
                        v0 = fmaxf(v0 + dg * bias[gn], 0.f);
                        v1 = fmaxf(v1 + dg * bias[gn + 1], 0.f);
                        C[(size_t)gm * Nc + gn] = v0;
                        C[(size_t)gm * Nc + gn + 1] = v1;
                    } else {
                        v0 += bias[gn];
                        v1 += bias[gn + 1];
                        *reinterpret_cast<__half2*>(Ch + (size_t)gm * Nc + gn) =
                            __floats2half2_rn(v0, v1);
                    }
                }
            }
        }
}

// ---------------- fused MLP (tf32): C[M,64] = prelu(A@W1+b1)@W3+b3 -------------------
// BM=256, 512 threads (16 warps: 8m x 2n). Weights double-buffered via cp.async.
__global__ __launch_bounds__(512, 1) void mlp_fused(const float* __restrict__ A,
                                                    const float* __restrict__ W1,
                                                    const float* __restrict__ b1,
                                                    const float* __restrict__ aptr,
                                                    const float* __restrict__ W3,
                                                    const float* __restrict__ b3,
                                                    float* __restrict__ C, int M) {
    extern __shared__ unsigned sm[];
    unsigned(*As)[68] = (unsigned(*)[68])sm;
    unsigned(*Hs)[68] = (unsigned(*)[68])(sm + 256 * 68);
    const unsigned W1_OFF = 2 * 256 * 68;
    const unsigned W3_OFF = W1_OFF + 2 * 64 * 72;
    float(*W1s)[64][72] = (float(*)[64][72])(sm + W1_OFF);
    float(*W3s)[64][72] = (float(*)[64][72])(sm + W3_OFF);

    const int tid = threadIdx.x, lane = tid & 31, wid = tid >> 5;
    const int bm = blockIdx.x * 256;
    const int m_base = (wid & 7) * 32, n_base = (wid >> 3) * 32;
    const int lr = lane >> 2, lk = lane & 3;
    const float alpha = aptr[0];
    const unsigned sb = (unsigned)__cvta_generic_to_shared(sm);

#pragma unroll
    for (int p = 0; p < 8; p++) {
        int idx = tid + p * 512;
        int row = idx >> 4, q = idx & 15;
        float4 v = make_float4(0.f, 0.f, 0.f, 0.f);
        if (bm + row < M)
            v = *reinterpret_cast<const float4*>(A + (size_t)(bm + row) * 64 + q * 4);
        As[row][q * 4 + 0] = cvt_tf32(v.x);
        As[row][q * 4 + 1] = cvt_tf32(v.y);
        As[row][q * 4 + 2] = cvt_tf32(v.z);
        As[row][q * 4 + 3] = cvt_tf32(v.w);
    }

    auto issue = [&](int ch, int buf) {
#pragma unroll
        for (int j = 0; j < 2; j++) {
            int idx = tid + j * 512;
            int k = idx >> 4, q = idx & 15;
            const float* g1 = W1 + (size_t)k * 512 + ch * 64 + q * 4;
            unsigned d1 = sb + (W1_OFF + (unsigned)buf * 64 * 72 + k * 72 + q * 4) * 4u;
            CP16(d1, g1);
            const float* g3 = W3 + (size_t)(ch * 64 + k) * 64 + q * 4;
            unsigned d3 = sb + (W3_OFF + (unsigned)buf * 64 * 72 + k * 72 + q * 4) * 4u;
            CP16(d3, g3);
        }
        CP_COMMIT();
    };
    issue(0, 0);

    float out_acc[2][4][4];
#pragma unroll
    for (int mi = 0; mi < 2; mi++)
#pragma unroll
        for (int ni = 0; ni < 4; ni++)
#pragma unroll
            for (int i = 0; i < 4; i++) out_acc[mi][ni][i] = 0.f;

    for (int ch = 0; ch < 8; ch++) {
        const int buf = ch & 1;
        CP_WAIT0();
        __syncthreads();
        if (ch < 7) issue(ch + 1, buf ^ 1);

        float h_acc[2][4][4];
#pragma unroll
        for (int mi = 0; mi < 2; mi++)
#pragma unroll
            for (int ni = 0; ni < 4; ni++)
#pragma unroll
                for (int i = 0; i < 4; i++) h_acc[mi][ni][i] = 0.f;

#pragma unroll
        for (int kk = 0; kk < 8; kk++) {
            unsigned a[2][4], b[4][2];
#pragma unroll
            for (int mi = 0; mi < 2; mi++) {
                int r0 = m_base + mi * 16 + lr;
                a[mi][0] = As[r0][kk * 8 + lk];
                a[mi][1] = As[r0 + 8][kk * 8 + lk];
                a[mi][2] = As[r0][kk * 8 + lk + 4];
                a[mi][3] = As[r0 + 8][kk * 8 + lk + 4];
            }
#pragma unroll
            for (int ni = 0; ni < 4; ni++) {
                int cn = n_base + ni * 8 + lr;
                b[ni][0] = cvt_tf32(W1s[buf][kk * 8 + lk][cn]);
                b[ni][1] = cvt_tf32(W1s[buf][kk * 8 + lk + 4][cn]);
            }
#pragma unroll
            for (int mi = 0; mi < 2; mi++)
#pragma unroll
                for (int ni = 0; ni < 4; ni++) mma8(h_acc[mi][ni], a[mi], b[ni]);
        }

#pragma unroll
        for (int mi = 0; mi < 2; mi++)
#pragma unroll
            for (int ni = 0; ni < 4; ni++)
#pragma unroll
                for (int i = 0; i < 4; i++) {
                    int row = m_base + mi * 16 + lr + ((i >= 2) ? 8 : 0);
                    int col = n_base + ni * 8 + 2 * lk + (i & 1);
                    float v = h_acc[mi][ni][i] + b1[ch * 64 + col];
                    v = (v >= 0.f) ? v : alpha * v;
                    Hs[row][col] = cvt_tf32(v);
                }
        __syncthreads();

#pragma unroll
        for (int kk = 0; kk < 8; kk++) {
            unsigned a[2][4], b[4][2];
#pragma unroll
            for (int mi = 0; mi < 2; mi++) {
                int r0 = m_base + mi * 16 + lr;
                a[mi][0] = Hs[r0][kk * 8 + lk];
                a[mi][1] = Hs[r0 + 8][kk * 8 + lk];
                a[mi][2] = Hs[r0][kk * 8 + lk + 4];
                a[mi][3] = Hs[r0 + 8][kk * 8 + lk + 4];
            }
#pragma unroll
            for (int ni = 0; ni < 4; ni++) {
                int cn = n_base + ni * 8 + lr;
                b[ni][0] = cvt_tf32(W3s[buf][kk * 8 + lk][cn]);
                b[ni][1] = cvt_tf32(W3s[buf][kk * 8 + lk + 4][cn]);
            }
#pragma unroll
            for (int mi = 0; mi < 2; mi++)
#pragma unroll
                for (int ni = 0; ni < 4; ni++) mma8(out_acc[mi][ni], a[mi], b[ni]);
        }
    }

#pragma unroll
    for (int mi = 0; mi < 2; mi++)
#pragma unroll
        for (int ni = 0; ni < 4; ni++)
#pragma unroll
            for (int i = 0; i < 4; i++) {
                int row = m_base + mi * 16 + lr + ((i >= 2) ? 8 : 0);
                int col = n_base + ni * 8 + 2 * lk + (i & 1);
                int gm = bm + row;
                if (gm < M) C[(size_t)gm * 64 + col] = out_acc[mi][ni][i] + b3[col];
            }
}

// ---------------- relu slots 0..2 in place; emit fp16 copies of slots 0,1 ------------
__global__ void relu_emit_half(float4* __restrict__ p, __half* __restrict__ h0,
                               __half* __restrict__ h1, int n4) {
    int i = blockIdx.x * blockDim.x + threadIdx.x;
    if (i < n4) {
        float4 v = p[i];
        v.x = fmaxf(v.x, 0.f);
        v.y = fmaxf(v.y, 0.f);
        v.z = fmaxf(v.z, 0.f);
        v.w = fmaxf(v.w, 0.f);
        p[i] = v;
        const int per_slot = NN * 16;
        if (i < 2 * per_slot) {
            __half* dst = (i < per_slot) ? h0 : h1;
            int off = (i < per_slot) ? i : i - per_slot;
            __half2 a = __floats2half2_rn(v.x, v.y);
            __half2 b = __floats2half2_rn(v.z, v.w);
            uint2 u;
            u.x = *reinterpret_cast<unsigned*>(&a);
            u.y = *reinterpret_cast<unsigned*>(&b);
            *reinterpret_cast<uint2*>(dst + (size_t)off * 4) = u;
        }
    }
}

// ---------------- sigmoid(buf / max(deg,1)) over slots 3,4 ----------------
__global__ void sigavg2_kernel(float* __restrict__ b3, float* __restrict__ b4,
                               const float* __restrict__ degN, const float* __restrict__ degD) {
    int i = blockIdx.x * blockDim.x + threadIdx.x;
    const int n = NN * 64;
    if (i < 2 * n) {
        float* buf = (i < n) ? b3 : b4;
        const float* deg = (i < n) ? degN : degD;
        int j = (i < n) ? i : i - n;
        float d = deg[j >> 6];
        d = (d > 1.f) ? d : 1.f;
        float x = buf[j] / d;
        buf[j] = 1.f / (1.f + expf(-x));
    }
}

// ---------------- discriminator ----------------
__global__ void disc_kernel(const float* __restrict__ Mo, const float* __restrict__ W,
                            const float* __restrict__ bptr, float* __restrict__ ret,
                            float* __restrict__ ret_a) {
    __shared__ float Ws[64][65];
    int tid = threadIdx.x;
    for (int i = tid; i < 4096; i += 128) Ws[i >> 6][i & 63] = W[i];
    __syncthreads();

    int warp = tid >> 5, lane = tid & 31;
    int node = blockIdx.x * 4 + warp;
    if (node >= NN) return;

    const float* z = Mo + (size_t)0 * NN * 64 + (size_t)node * 64;
    const float* zg = Mo + (size_t)1 * NN * 64 + (size_t)node * 64;
    const float* sz = Mo + (size_t)2 * NN * 64 + (size_t)node * 64;
    const float* gv = Mo + (size_t)3 * NN * 64 + (size_t)node * 64;
    const float* gg = Mo + (size_t)4 * NN * 64 + (size_t)node * 64;

    float r0 = 0.f, r1 = 0.f, a0 = 0.f, a1 = 0.f;
#pragma unroll
    for (int h = 0; h < 2; h++) {
        int d = lane + h * 32;
        float tgg = 0.f, tg = 0.f;
#pragma unroll
        for (int e = 0; e < 64; e++) {
            float w = Ws[d][e];
            tgg += w * gg[e];
            tg += w * gv[e];
        }
        r0 += z[d] * tgg;
        r1 += sz[d] * tgg;
        a0 += zg[d] * tg;
        a1 += sz[d] * tg;
    }
#pragma unroll
    for (int o = 16; o; o >>= 1) {
        r0 += __shfl_xor_sync(0xFFFFFFFFu, r0, o);
        r1 += __shfl_xor_sync(0xFFFFFFFFu, r1, o);
        a0 += __shfl_xor_sync(0xFFFFFFFFu, a0, o);
        a1 += __shfl_xor_sync(0xFFFFFFFFu, a1, o);
    }
    if (lane == 0) {
        float b = bptr[0];
        ret[(size_t)node * 2 + 0] = r0 + b;
        ret[(size_t)node * 2 + 1] = r1 + b;
        ret_a[(size_t)node * 2 + 0] = a0 + b;
        ret_a[(size_t)node * 2 + 1] = a1 + b;
    }
}

// =====================================================================================
extern "C" void kernel_launch(void* const* d_in, const int* in_sizes, int n_in, void* d_out,
                              int out_size) {
    (void)in_sizes; (void)n_in; (void)out_size;

    const float* feat      = (const float*)d_in[0];
    const int*   adj_src   = (const int*)d_in[1];
    const int*   adj_dst   = (const int*)d_in[2];
    const float* adj_val   = (const float*)d_in[3];
    const int*   gdc_src   = (const int*)d_in[4];
    const int*   gdc_dst   = (const int*)d_in[5];
    const float* gdc_val   = (const float*)d_in[6];
    const int*   neigh_src = (const int*)d_in[7];
    const int*   neigh_dst = (const int*)d_in[8];
    const float* neigh_val = (const float*)d_in[9];
    const int*   diff_src  = (const int*)d_in[10];
    const int*   diff_dst  = (const int*)d_in[11];
    const float* diff_val  = (const float*)d_in[12];
    const int*   perm      = (const int*)d_in[13];
    const float* W_enc     = (const float*)d_in[14];
    const float* b_enc     = (const float*)d_in[15];
    const float* W_dec     = (const float*)d_in[16];
    const float* b_dec     = (const float*)d_in[17];
    const float* W1        = (const float*)d_in[18];
    const float* b1        = (const float*)d_in[19];
    const float* prelu_a   = (const float*)d_in[20];
    const float* W3        = (const float*)d_in[21];
    const float* b3        = (const float*)d_in[22];
    const float* W_disc    = (const float*)d_in[23];
    const float* b_disc    = (const float*)d_in[24];

    int *CNTp, *ROWPTRp, *CURp, *ESRCp, *EDSTp, *EPDp;
    float *EVALp, *Sp, *MLPINp, *MLPOUTp, *DEGp;
    __half *Xhp, *Hh0p, *Hh1p;
    cudaGetSymbolAddress((void**)&CNTp, g_CNT);
    cudaGetSymbolAddress((void**)&ROWPTRp, g_ROWPTR);
    cudaGetSymbolAddress((void**)&CURp, g_CUR);
    cudaGetSymbolAddress((void**)&ESRCp, g_ESRC);
    cudaGetSymbolAddress((void**)&EDSTp, g_EDST);
    cudaGetSymbolAddress((void**)&EVALp, g_EVAL);
    cudaGetSymbolAddress((void**)&EPDp, g_EPD);
    cudaGetSymbolAddress((void**)&Xhp, g_Xh);
    cudaGetSymbolAddress((void**)&Hh0p, g_Hh0);
    cudaGetSymbolAddress((void**)&Hh1p, g_Hh1);
    cudaGetSymbolAddress((void**)&Sp, g_S);
    cudaGetSymbolAddress((void**)&MLPINp, g_MLPIN);
    cudaGetSymbolAddress((void**)&MLPOUTp, g_MLPOUT);
    cudaGetSymbolAddress((void**)&DEGp, g_DEG);

    float* out = (float*)d_out;
    float* emb = out;                       // [NN,256]
    float* ret = out + (size_t)NN * 256;    // [NN,2]
    float* ret_a = ret + (size_t)NN * 2;    // [NN,2]

    const int MLP_SMEM = (2 * 256 * 68 + 4 * 64 * 72) * 4;  // 212992
    static bool attr_set = false;
    if (!attr_set) {
        cudaFuncSetAttribute(mlp_fused, cudaFuncAttributeMaxDynamicSharedMemorySize, MLP_SMEM);
        attr_set = true;
    }

    const int MROWS = (NN + 127) / 128;                              // 391
    const int EB = (EE + 255) / 256;
    const unsigned seg_blocks = ((unsigned)EE * 4u + 255u) / 256u;   // 12500

    // zero accumulators
    cudaMemsetAsync(CNTp, 0, (size_t)NG4 * sizeof(int));
    cudaMemsetAsync(MLPINp, 0, (size_t)5 * NN * 64 * sizeof(float));
    cudaMemsetAsync(Sp, 0, (size_t)NN * 64 * sizeof(float));
    cudaMemsetAsync(DEGp, 0, (size_t)3 * NN * sizeof(float));

    // ---- CSR build (edges sorted by src per graph) ----
    hist4<<<EB, 256>>>(adj_src, gdc_src, neigh_src, diff_src, CNTp);
    scan_kernel<<<1, 1024>>>(CNTp, ROWPTRp, CURp);
    scatter4<<<EB, 256>>>(adj_src, adj_dst, adj_val, gdc_src, gdc_dst, gdc_val, neigh_src,
                          neigh_dst, neigh_val, diff_src, diff_dst, diff_val, perm, CURp, ESRCp,
                          EDSTp, EVALp, EPDp);

    // ---- encoder: Xh = half(feat @ W_enc + b_enc), tf32 ----
    mma_gemm<2><<<dim3(1, MROWS), 256>>>(feat, W_enc, b_enc, nullptr, nullptr, Xhp, NN, 256, 64);

    // ---- stage 1: adj dual (h slot0, shuf_h slot2, degA), gdc (h_g slot1) ----
    spmm_seg_dual<<<seg_blocks, 256>>>(ESRCp, EDSTp, EVALp, EPDp, Xhp,
                                       MLPINp + (size_t)0 * NN * 64,
                                       MLPINp + (size_t)2 * NN * 64, DEGp, EE);
    spmm_seg<<<seg_blocks, 256>>>(ESRCp + EE, EDSTp + EE, EVALp + EE, Xhp,
                                  MLPINp + (size_t)1 * NN * 64, nullptr, EE);

    // ---- relu slots 0..2 in place; fp16 copies of relu(h), relu(h_g) ----
    {
        int n4 = 3 * NN * 16;
        relu_emit_half<<<(n4 + 255) / 256, 256>>>((float4*)MLPINp, Hh0p, Hh1p, n4);
    }

    // ---- stage 2: adj over relu(h) -> S; neigh -> slot3 (+degN); diff -> slot4 (+degD)
    spmm_seg<<<seg_blocks, 256>>>(ESRCp, EDSTp, EVALp, Hh0p, Sp, nullptr, EE);
    spmm_seg<<<seg_blocks, 256>>>(ESRCp + 2 * EE, EDSTp + 2 * EE, EVALp + 2 * EE, Hh0p,
                                  MLPINp + (size_t)3 * NN * 64, DEGp + NN, EE);
    spmm_seg<<<seg_blocks, 256>>>(ESRCp + 3 * EE, EDSTp + 3 * EE, EVALp + 3 * EE, Hh1p,
                                  MLPINp + (size_t)4 * NN * 64, DEGp + 2 * NN, EE);

    // ---- emb = relu(S @ W_dec + deg_adj ⊗ b_dec)  (spmm linearity), tf32 ----
    mma_gemm<1><<<dim3(4, MROWS), 256>>>(Sp, W_dec, b_dec, DEGp, emb, nullptr, NN, 64, 256);

    // ---- sigmoid averages for slots 3,4 ----
    {
        int n2 = 2 * NN * 64;
        sigavg2_kernel<<<(n2 + 255) / 256, 256>>>(MLPINp + (size_t)3 * NN * 64,
                                                  MLPINp + (size_t)4 * NN * 64, DEGp + NN,
                                                  DEGp + 2 * NN);
    }

    // ---- fused batched MLP over all 5 inputs (tf32 + cp.async) ----
    {
        int M = 5 * NN;
        mlp_fused<<<(M + 255) / 256, 512, MLP_SMEM>>>(MLPINp, W1, b1, prelu_a, W3, b3, MLPOUTp, M);
    }

    // ---- discriminator heads ----
    disc_kernel<<<(NN + 3) / 4, 128>>>(MLPOUTp, W_disc, b_disc, ret, ret_a);
}

// round 9
// speedup vs baseline: 1.4678x; 1.4678x over previous
#include <cuda_runtime.h>
#include <cuda_fp16.h>
#include <math.h>

#define NN 50000
#define EE 800000

// ---------------- scratch (static device globals; no runtime alloc) ----------------
__device__ __half g_Xh[(size_t)NN * 64];          // feat@W_enc + b_enc (fp16, gather-only)
__device__ __half g_Hh0[(size_t)NN * 64];         // relu(h)   fp16 (gather copy)
__device__ __half g_Hh1[(size_t)NN * 64];         // relu(h_g) fp16 (gather copy)
__device__ float g_S[(size_t)NN * 64];            // spmm(adj, relu_h)
__device__ float g_MLPIN[(size_t)5 * NN * 64];    // h, h_g, shuf_h, sig_neigh, sig_diff
__device__ float g_MLPOUT[(size_t)5 * NN * 64];   // z, z_g, shuf_z, g, g_g
__device__ float g_DEG[3 * NN];                   // [adj | neigh | diff]
__device__ __half g_W1T[512 * 64];                // W1 transposed: [n_hid][k_in] fp16
__device__ __half g_W3T[64 * 512];                // W3 transposed: [n_out][k_hid] fp16

// ---------------- tf32 helpers ----------------
__device__ __forceinline__ unsigned cvt_tf32(float x) {
    unsigned u;
    asm("cvt.rna.tf32.f32 %0, %1;" : "=r"(u) : "f"(x));
    return u;
}
__device__ __forceinline__ void mma8(float* c, const unsigned* a, const unsigned* b) {
    asm("mma.sync.aligned.m16n8k8.row.col.f32.tf32.tf32.f32 "
        "{%0,%1,%2,%3},{%4,%5,%6,%7},{%8,%9},{%0,%1,%2,%3};"
        : "+f"(c[0]), "+f"(c[1]), "+f"(c[2]), "+f"(c[3])
        : "r"(a[0]), "r"(a[1]), "r"(a[2]), "r"(a[3]), "r"(b[0]), "r"(b[1]));
}
// fp16 m16n8k16 mma, fp32 accumulate
__device__ __forceinline__ void mma16(float* c, const unsigned* a, const unsigned* b) {
    asm("mma.sync.aligned.m16n8k16.row.col.f32.f16.f16.f32 "
        "{%0,%1,%2,%3},{%4,%5,%6,%7},{%8,%9},{%0,%1,%2,%3};"
        : "+f"(c[0]), "+f"(c[1]), "+f"(c[2]), "+f"(c[3])
        : "r"(a[0]), "r"(a[1]), "r"(a[2]), "r"(a[3]), "r"(b[0]), "r"(b[1]));
}

#define CP16(sdst, gsrc) \
    asm volatile("cp.async.ca.shared.global [%0], [%1], 16;" ::"r"(sdst), "l"(gsrc))
#define CP_COMMIT() asm volatile("cp.async.commit_group;")
#define CP_WAIT0() asm volatile("cp.async.wait_group 0;" ::: "memory")

// ---------------- weight pre-transpose (fp32 -> fp16, [k][n] -> [n][k]) --------------
// block 0 (512 thr): W1T[n][k] = W1[k][n], n<512, k<64
// block 1 (512 thr): W3T[n][k] = W3[k][n], n<64,  k<512 (8 k-slabs x 64 n)
__global__ void transpose_w(const float* __restrict__ W1, const float* __restrict__ W3,
                            __half* __restrict__ W1T, __half* __restrict__ W3T) {
    int t = threadIdx.x;
    if (blockIdx.x == 0) {
        int n = t;  // 0..511
#pragma unroll 4
        for (int k = 0; k < 64; k++) W1T[n * 64 + k] = __float2half_rn(W1[k * 512 + n]);
    } else {
        int n = t & 63;
        int kb = (t >> 6) * 64;  // 8 slabs
#pragma unroll 4
        for (int k = kb; k < kb + 64; k++) W3T[n * 512 + k] = __float2half_rn(W3[k * 64 + n]);
    }
}

// ---------------- single-TF32 GEMM ----------------
// BM=128, BN=64, BK=32, 256 threads (8 warps: 4m x 2n).
// EPI 1: C = relu(acc + deg[m]*bias[n])   (fp32 out)
// EPI 2: Ch = half(acc + bias[n])          (fp16 out)
template <int EPI>
__global__ __launch_bounds__(256) void mma_gemm(const float* __restrict__ A,
                                                const float* __restrict__ W,
                                                const float* __restrict__ bias,
                                                const float* __restrict__ deg,
                                                float* __restrict__ C, __half* __restrict__ Ch,
                                                int M, int K, int Nc) {
    __shared__ unsigned As[128][36];
    __shared__ unsigned Bs[32][72];

    const int tid = threadIdx.x, lane = tid & 31, wid = tid >> 5;
    const int bm = blockIdx.y * 128, bn0 = blockIdx.x * 64;
    const int m_base = (wid & 3) * 32, n_base = (wid >> 2) * 32;
    const int lr = lane >> 2, lk = lane & 3;

    float acc[2][4][4];
#pragma unroll
    for (int mi = 0; mi < 2; mi++)
#pragma unroll
        for (int ni = 0; ni < 4; ni++)
#pragma unroll
            for (int i = 0; i < 4; i++) acc[mi][ni][i] = 0.f;

    for (int k0 = 0; k0 < K; k0 += 32) {
#pragma unroll
        for (int p = 0; p < 4; p++) {
            int idx = tid + p * 256;
            int row = idx >> 3, q = idx & 7;
            float4 v = make_float4(0.f, 0.f, 0.f, 0.f);
            if (bm + row < M)
                v = *reinterpret_cast<const float4*>(A + (size_t)(bm + row) * K + k0 + q * 4);
            As[row][q * 4 + 0] = cvt_tf32(v.x);
            As[row][q * 4 + 1] = cvt_tf32(v.y);
            As[row][q * 4 + 2] = cvt_tf32(v.z);
            As[row][q * 4 + 3] = cvt_tf32(v.w);
        }
#pragma unroll
        for (int p = 0; p < 2; p++) {
            int idx = tid + p * 256;
            int kr = idx >> 4, q = idx & 15;
            float4 v = *reinterpret_cast<const float4*>(W + (size_t)(k0 + kr) * Nc + bn0 + q * 4);
            Bs[kr][q * 4 + 0] = cvt_tf32(v.x);
            Bs[kr][q * 4 + 1] = cvt_tf32(v.y);
            Bs[kr][q * 4 + 2] = cvt_tf32(v.z);
            Bs[kr][q * 4 + 3] = cvt_tf32(v.w);
        }
        __syncthreads();

#pragma unroll
        for (int kk = 0; kk < 4; kk++) {
            unsigned a[2][4], b[4][2];
#pragma unroll
            for (int mi = 0; mi < 2; mi++) {
                int r0 = m_base + mi * 16 + lr;
                a[mi][0] = As[r0][kk * 8 + lk];
                a[mi][1] = As[r0 + 8][kk * 8 + lk];
                a[mi][2] = As[r0][kk * 8 + lk + 4];
                a[mi][3] = As[r0 + 8][kk * 8 + lk + 4];
            }
#pragma unroll
            for (int ni = 0; ni < 4; ni++) {
                int cn = n_base + ni * 8 + lr;
                b[ni][0] = Bs[kk * 8 + lk][cn];
                b[ni][1] = Bs[kk * 8 + lk + 4][cn];
            }
#pragma unroll
            for (int mi = 0; mi < 2; mi++)
#pragma unroll
                for (int ni = 0; ni < 4; ni++) mma8(acc[mi][ni], a[mi], b[ni]);
        }
        __syncthreads();
    }

#pragma unroll
    for (int mi = 0; mi < 2; mi++)
#pragma unroll
        for (int ni = 0; ni < 4; ni++) {
#pragma unroll
            for (int hi = 0; hi < 2; hi++) {
                int row = m_base + mi * 16 + lr + hi * 8;
                int col = n_base + ni * 8 + 2 * lk;
                int gm = bm + row, gn = bn0 + col;
                if (gm < M) {
                    float v0 = acc[mi][ni][hi * 2 + 0];
                    float v1 = acc[mi][ni][hi * 2 + 1];
                    if (EPI == 1) {
                        float dg = deg[gm];
                        v0 = fmaxf(v0 + dg * bias[gn], 0.f);
                        v1 = fmaxf(v1 + dg * bias[gn + 1], 0.f);
                        C[(size_t)gm * Nc + gn] = v0;
                        C[(size_t)gm * Nc + gn + 1] = v1;
                    } else {
                        v0 += bias[gn];
                        v1 += bias[gn + 1];
                        *reinterpret_cast<__half2*>(Ch + (size_t)gm * Nc + gn) =
                            __floats2half2_rn(v0, v1);
                    }
                }
            }
        }
}

// ---------------- fused MLP v2 (fp16 mma, pre-transposed weights, cp.async) ----------
// BM=256, 512 threads (16 warps: 8m x 2n, warp tile 32x32), m16n8k16.
// smem (halves): As 256x72, Hs 256x72, W1s 2x64x72, W3s 2x64x72 = 110592 B. 1 CTA/SM,
// full register budget (no spills).
__global__ __launch_bounds__(512, 1) void mlp16(const float* __restrict__ A,
                                                const __half* __restrict__ W1T,
                                                const float* __restrict__ b1,
                                                const float* __restrict__ aptr,
                                                const __half* __restrict__ W3T,
                                                const float* __restrict__ b3,
                                                float* __restrict__ C, int M) {
    extern __shared__ __half hsm[];
    __half(*As)[72] = (__half(*)[72])hsm;
    __half(*Hs)[72] = (__half(*)[72])(hsm + 256 * 72);
    const unsigned W1_OFF = 2 * 256 * 72;                 // in halves
    const unsigned W3_OFF = W1_OFF + 2 * 64 * 72;
    __half(*W1s)[64][72] = (__half(*)[64][72])(hsm + W1_OFF);
    __half(*W3s)[64][72] = (__half(*)[64][72])(hsm + W3_OFF);

    const int tid = threadIdx.x, lane = tid & 31, wid = tid >> 5;
    const int bm = blockIdx.x * 256;
    const int m_base = (wid & 7) * 32, n_base = (wid >> 3) * 32;
    const int g = lane >> 2, t = lane & 3;
    const float alpha = aptr[0];
    const unsigned sb = (unsigned)__cvta_generic_to_shared(hsm);

    // weight chunk prefetch: contiguous fp16 rows via cp.async (row stride 144B = 16*9)
    auto issue = [&](int ch, int buf) {
        int n = tid >> 3, o = tid & 7;  // n: 0..63, o: 16B chunk within 128B row
        const __half* s1 = W1T + ((size_t)(ch * 64 + n)) * 64 + o * 8;
        unsigned d1 = sb + (W1_OFF + (unsigned)buf * 64 * 72 + n * 72 + o * 8) * 2u;
        CP16(d1, s1);
        const __half* s3 = W3T + (size_t)n * 512 + ch * 64 + o * 8;
        unsigned d3 = sb + (W3_OFF + (unsigned)buf * 64 * 72 + n * 72 + o * 8) * 2u;
        CP16(d3, s3);
        CP_COMMIT();
    };
    issue(0, 0);

    // A tile 256x64: fp32 -> fp16 (resident)
#pragma unroll
    for (int p = 0; p < 8; p++) {
        int idx = tid + p * 512;
        int row = idx >> 4, q = idx & 15;
        float4 v = make_float4(0.f, 0.f, 0.f, 0.f);
        if (bm + row < M)
            v = *reinterpret_cast<const float4*>(A + (size_t)(bm + row) * 64 + q * 4);
        *reinterpret_cast<__half2*>(&As[row][q * 4]) = __floats2half2_rn(v.x, v.y);
        *reinterpret_cast<__half2*>(&As[row][q * 4 + 2]) = __floats2half2_rn(v.z, v.w);
    }

    float out_acc[2][4][4];
#pragma unroll
    for (int mi = 0; mi < 2; mi++)
#pragma unroll
        for (int ni = 0; ni < 4; ni++)
#pragma unroll
            for (int i = 0; i < 4; i++) out_acc[mi][ni][i] = 0.f;

    for (int ch = 0; ch < 8; ch++) {
        const int buf = ch & 1;
        CP_WAIT0();
        __syncthreads();  // weights(ch) + As visible; Hs free
        if (ch < 7) issue(ch + 1, buf ^ 1);

        // stage 1: h = A @ W1chunk  (4 k-iters of 16)
        float h_acc[2][4][4];
#pragma unroll
        for (int mi = 0; mi < 2; mi++)
#pragma unroll
            for (int ni = 0; ni < 4; ni++)
#pragma unroll
                for (int i = 0; i < 4; i++) h_acc[mi][ni][i] = 0.f;

#pragma unroll
        for (int kk = 0; kk < 4; kk++) {
            unsigned a[2][4], b[4][2];
#pragma unroll
            for (int mi = 0; mi < 2; mi++) {
                int r0 = m_base + mi * 16 + g;
                a[mi][0] = *reinterpret_cast<const unsigned*>(&As[r0][kk * 16 + 2 * t]);
                a[mi][1] = *reinterpret_cast<const unsigned*>(&As[r0 + 8][kk * 16 + 2 * t]);
                a[mi][2] = *reinterpret_cast<const unsigned*>(&As[r0][kk * 16 + 2 * t + 8]);
                a[mi][3] = *reinterpret_cast<const unsigned*>(&As[r0 + 8][kk * 16 + 2 * t + 8]);
            }
#pragma unroll
            for (int ni = 0; ni < 4; ni++) {
                int cn = n_base + ni * 8 + g;
                b[ni][0] = *reinterpret_cast<const unsigned*>(&W1s[buf][cn][kk * 16 + 2 * t]);
                b[ni][1] = *reinterpret_cast<const unsigned*>(&W1s[buf][cn][kk * 16 + 2 * t + 8]);
            }
#pragma unroll
            for (int mi = 0; mi < 2; mi++)
#pragma unroll
                for (int ni = 0; ni < 4; ni++) mma16(h_acc[mi][ni], a[mi], b[ni]);
        }

        // bias + prelu -> Hs (fp16)
#pragma unroll
        for (int mi = 0; mi < 2; mi++)
#pragma unroll
            for (int ni = 0; ni < 4; ni++) {
                int r0 = m_base + mi * 16 + g;
                int hc = n_base + ni * 8 + 2 * t;
                float bb0 = b1[ch * 64 + hc], bb1 = b1[ch * 64 + hc + 1];
                float v0 = h_acc[mi][ni][0] + bb0;
                float v1 = h_acc[mi][ni][1] + bb1;
                float v2 = h_acc[mi][ni][2] + bb0;
                float v3 = h_acc[mi][ni][3] + bb1;
                v0 = (v0 >= 0.f) ? v0 : alpha * v0;
                v1 = (v1 >= 0.f) ? v1 : alpha * v1;
                v2 = (v2 >= 0.f) ? v2 : alpha * v2;
                v3 = (v3 >= 0.f) ? v3 : alpha * v3;
                *reinterpret_cast<__half2*>(&Hs[r0][hc]) = __floats2half2_rn(v0, v1);
                *reinterpret_cast<__half2*>(&Hs[r0 + 8][hc]) = __floats2half2_rn(v2, v3);
            }
        __syncthreads();

        // stage 2: out += H @ W3chunk
#pragma unroll
        for (int kk = 0; kk < 4; kk++) {
            unsigned a[2][4], b[4][2];
#pragma unroll
            for (int mi = 0; mi < 2; mi++) {
                int r0 = m_base + mi * 16 + g;
                a[mi][0] = *reinterpret_cast<const unsigned*>(&Hs[r0][kk * 16 + 2 * t]);
                a[mi][1] = *reinterpret_cast<const unsigned*>(&Hs[r0 + 8][kk * 16 + 2 * t]);
                a[mi][2] = *reinterpret_cast<const unsigned*>(&Hs[r0][kk * 16 + 2 * t + 8]);
                a[mi][3] = *reinterpret_cast<const unsigned*>(&Hs[r0 + 8][kk * 16 + 2 * t + 8]);
            }
#pragma unroll
            for (int ni = 0; ni < 4; ni++) {
                int cn = n_base + ni * 8 + g;
                b[ni][0] = *reinterpret_cast<const unsigned*>(&W3s[buf][cn][kk * 16 + 2 * t]);
                b[ni][1] = *reinterpret_cast<const unsigned*>(&W3s[buf][cn][kk * 16 + 2 * t + 8]);
            }
#pragma unroll
            for (int mi = 0; mi < 2; mi++)
#pragma unroll
                for (int ni = 0; ni < 4; ni++) mma16(out_acc[mi][ni], a[mi], b[ni]);
        }
    }

    // epilogue
#pragma unroll
    for (int mi = 0; mi < 2; mi++)
#pragma unroll
        for (int ni = 0; ni < 4; ni++)
#pragma unroll
            for (int i = 0; i < 4; i++) {
                int row = m_base + mi * 16 + g + ((i >= 2) ? 8 : 0);
                int col = n_base + ni * 8 + 2 * t + (i & 1);
                int gm = bm + row;
                if (gm < M) C[(size_t)gm * 64 + col] = out_acc[mi][ni][i] + b3[col];
            }
}

// ---------------- fp16-gather SpMM (4 thr/edge, 16 cols each) ----------------
__device__ __forceinline__ void gather8(const __half* base, unsigned off, float* f) {
    uint4 u = *reinterpret_cast<const uint4*>(base + off);
    const __half2* h = reinterpret_cast<const __half2*>(&u);
#pragma unroll
    for (int i = 0; i < 4; i++) {
        float2 a = __half22float2(h[i]);
        f[2 * i] = a.x;
        f[2 * i + 1] = a.y;
    }
}
__device__ __forceinline__ void red4(float* p, float a, float b, float c, float d) {
    asm volatile("red.global.add.v4.f32 [%0], {%1,%2,%3,%4};" ::"l"(p), "f"(a), "f"(b), "f"(c),
                 "f"(d)
                 : "memory");
}

__global__ void spmm64h(const int* __restrict__ src, const int* __restrict__ dst,
                        const float* __restrict__ val, const __half* __restrict__ X,
                        float* __restrict__ out, int E) {
    unsigned gid = blockIdx.x * blockDim.x + threadIdx.x;
    unsigned e = gid >> 2;
    if (e >= (unsigned)E) return;
    unsigned c = gid & 3;
    int s = src[e];
    int d = dst[e];
    float v = val[e];
    float f[16];
    gather8(X, (unsigned)d * 64 + c * 16, f);
    gather8(X, (unsigned)d * 64 + c * 16 + 8, f + 8);
    float* p = out + (size_t)s * 64 + c * 16;
#pragma unroll
    for (int i = 0; i < 4; i++)
        red4(p + 4 * i, v * f[4 * i], v * f[4 * i + 1], v * f[4 * i + 2], v * f[4 * i + 3]);
}

// adj + shuffled-adj in one pass (shares index loads)
__global__ void spmm64h_dual(const int* __restrict__ src, const int* __restrict__ dst,
                             const float* __restrict__ val, const int* __restrict__ perm,
                             const __half* __restrict__ X, float* __restrict__ out0,
                             float* __restrict__ out1, int E) {
    unsigned gid = blockIdx.x * blockDim.x + threadIdx.x;
    unsigned e = gid >> 2;
    if (e >= (unsigned)E) return;
    unsigned c = gid & 3;
    int s = src[e];
    int d = dst[e];
    float v = val[e];
    int pd = perm[d];
    float f0[16], f1[16];
    gather8(X, (unsigned)d * 64 + c * 16, f0);
    gather8(X, (unsigned)d * 64 + c * 16 + 8, f0 + 8);
    gather8(X, (unsigned)pd * 64 + c * 16, f1);
    gather8(X, (unsigned)pd * 64 + c * 16 + 8, f1 + 8);
    float* p0 = out0 + (size_t)s * 64 + c * 16;
    float* p1 = out1 + (size_t)s * 64 + c * 16;
#pragma unroll
    for (int i = 0; i < 4; i++) {
        red4(p0 + 4 * i, v * f0[4 * i], v * f0[4 * i + 1], v * f0[4 * i + 2], v * f0[4 * i + 3]);
        red4(p1 + 4 * i, v * f1[4 * i], v * f1[4 * i + 1], v * f1[4 * i + 2], v * f1[4 * i + 3]);
    }
}

// ---------------- fused degree kernel for 3 graphs ----------------
__global__ void deg3_kernel(const int* __restrict__ sA, const float* __restrict__ vA,
                            const int* __restrict__ sN, const float* __restrict__ vN,
                            const int* __restrict__ sD, const float* __restrict__ vD,
                            float* __restrict__ dd, int E) {
    int e = blockIdx.x * blockDim.x + threadIdx.x;
    if (e < E) {
        atomicAdd(&dd[sA[e]], vA[e]);
        atomicAdd(&dd[NN + sN[e]], vN[e]);
        atomicAdd(&dd[2 * NN + sD[e]], vD[e]);
    }
}

// ---------------- relu slots 0..2 in place; emit fp16 copies of slots 0,1 ------------
__global__ void relu_emit_half(float4* __restrict__ p, __half* __restrict__ h0,
                               __half* __restrict__ h1, int n4) {
    int i = blockIdx.x * blockDim.x + threadIdx.x;
    if (i < n4) {
        float4 v = p[i];
        v.x = fmaxf(v.x, 0.f);
        v.y = fmaxf(v.y, 0.f);
        v.z = fmaxf(v.z, 0.f);
        v.w = fmaxf(v.w, 0.f);
        p[i] = v;
        const int per_slot = NN * 16;
        if (i < 2 * per_slot) {
            __half* dst = (i < per_slot) ? h0 : h1;
            int off = (i < per_slot) ? i : i - per_slot;
            __half2 a = __floats2half2_rn(v.x, v.y);
            __half2 b = __floats2half2_rn(v.z, v.w);
            uint2 u;
            u.x = *reinterpret_cast<unsigned*>(&a);
            u.y = *reinterpret_cast<unsigned*>(&b);
            *reinterpret_cast<uint2*>(dst + (size_t)off * 4) = u;
        }
    }
}

// ---------------- sigmoid(buf / max(deg,1)) over slots 3,4 ----------------
__global__ void sigavg2_kernel(float* __restrict__ b3, float* __restrict__ b4,
                               const float* __restrict__ degN, const float* __restrict__ degD) {
    int i = blockIdx.x * blockDim.x + threadIdx.x;
    const int n = NN * 64;
    if (i < 2 * n) {
        float* buf = (i < n) ? b3 : b4;
        const float* deg = (i < n) ? degN : degD;
        int j = (i < n) ? i : i - n;
        float d = deg[j >> 6];
        d = (d > 1.f) ? d : 1.f;
        float x = buf[j] / d;
        buf[j] = 1.f / (1.f + expf(-x));
    }
}

// ---------------- discriminator ----------------
__global__ void disc_kernel(const float* __restrict__ Mo, const float* __restrict__ W,
                            const float* __restrict__ bptr, float* __restrict__ ret,
                            float* __restrict__ ret_a) {
    __shared__ float Ws[64][65];
    int tid = threadIdx.x;
    for (int i = tid; i < 4096; i += 128) Ws[i >> 6][i & 63] = W[i];
    __syncthreads();

    int warp = tid >> 5, lane = tid & 31;
    int node = blockIdx.x * 4 + warp;
    if (node >= NN) return;

    const float* z = Mo + (size_t)0 * NN * 64 + (size_t)node * 64;
    const float* zg = Mo + (size_t)1 * NN * 64 + (size_t)node * 64;
    const float* sz = Mo + (size_t)2 * NN * 64 + (size_t)node * 64;
    const float* gv = Mo + (size_t)3 * NN * 64 + (size_t)node * 64;
    const float* gg = Mo + (size_t)4 * NN * 64 + (size_t)node * 64;

    float r0 = 0.f, r1 = 0.f, a0 = 0.f, a1 = 0.f;
#pragma unroll
    for (int h = 0; h < 2; h++) {
        int d = lane + h * 32;
        float tgg = 0.f, tg = 0.f;
#pragma unroll
        for (int e = 0; e < 64; e++) {
            float w = Ws[d][e];
            tgg += w * gg[e];
            tg += w * gv[e];
        }
        r0 += z[d] * tgg;
        r1 += sz[d] * tgg;
        a0 += zg[d] * tg;
        a1 += sz[d] * tg;
    }
#pragma unroll
    for (int o = 16; o; o >>= 1) {
        r0 += __shfl_xor_sync(0xFFFFFFFFu, r0, o);
        r1 += __shfl_xor_sync(0xFFFFFFFFu, r1, o);
        a0 += __shfl_xor_sync(0xFFFFFFFFu, a0, o);
        a1 += __shfl_xor_sync(0xFFFFFFFFu, a1, o);
    }
    if (lane == 0) {
        float b = bptr[0];
        ret[(size_t)node * 2 + 0] = r0 + b;
        ret[(size_t)node * 2 + 1] = r1 + b;
        ret_a[(size_t)node * 2 + 0] = a0 + b;
        ret_a[(size_t)node * 2 + 1] = a1 + b;
    }
}

// =====================================================================================
extern "C" void kernel_launch(void* const* d_in, const int* in_sizes, int n_in, void* d_out,
                              int out_size) {
    (void)in_sizes; (void)n_in; (void)out_size;

    const float* feat      = (const float*)d_in[0];
    const int*   adj_src   = (const int*)d_in[1];
    const int*   adj_dst   = (const int*)d_in[2];
    const float* adj_val   = (const float*)d_in[3];
    const int*   gdc_src   = (const int*)d_in[4];
    const int*   gdc_dst   = (const int*)d_in[5];
    const float* gdc_val   = (const float*)d_in[6];
    const int*   neigh_src = (const int*)d_in[7];
    const int*   neigh_dst = (const int*)d_in[8];
    const float* neigh_val = (const float*)d_in[9];
    const int*   diff_src  = (const int*)d_in[10];
    const int*   diff_dst  = (const int*)d_in[11];
    const float* diff_val  = (const float*)d_in[12];
    const int*   perm      = (const int*)d_in[13];
    const float* W_enc     = (const float*)d_in[14];
    const float* b_enc     = (const float*)d_in[15];
    const float* W_dec     = (const float*)d_in[16];
    const float* b_dec     = (const float*)d_in[17];
    const float* W1        = (const float*)d_in[18];
    const float* b1        = (const float*)d_in[19];
    const float* prelu_a   = (const float*)d_in[20];
    const float* W3        = (const float*)d_in[21];
    const float* b3        = (const float*)d_in[22];
    const float* W_disc    = (const float*)d_in[23];
    const float* b_disc    = (const float*)d_in[24];

    __half *Xhp, *Hh0p, *Hh1p, *W1Tp, *W3Tp;
    float *Sp, *MLPINp, *MLPOUTp, *DEGp;
    cudaGetSymbolAddress((void**)&Xhp, g_Xh);
    cudaGetSymbolAddress((void**)&Hh0p, g_Hh0);
    cudaGetSymbolAddress((void**)&Hh1p, g_Hh1);
    cudaGetSymbolAddress((void**)&W1Tp, g_W1T);
    cudaGetSymbolAddress((void**)&W3Tp, g_W3T);
    cudaGetSymbolAddress((void**)&Sp, g_S);
    cudaGetSymbolAddress((void**)&MLPINp, g_MLPIN);
    cudaGetSymbolAddress((void**)&MLPOUTp, g_MLPOUT);
    cudaGetSymbolAddress((void**)&DEGp, g_DEG);

    float* out = (float*)d_out;
    float* emb = out;                       // [NN,256]
    float* ret = out + (size_t)NN * 256;    // [NN,2]
    float* ret_a = ret + (size_t)NN * 2;    // [NN,2]

    const int MLP_SMEM = (2 * 256 * 72 + 4 * 64 * 72) * 2;  // 110592 B
    static bool attr_set = false;
    if (!attr_set) {
        cudaFuncSetAttribute(mlp16, cudaFuncAttributeMaxDynamicSharedMemorySize, MLP_SMEM);
        attr_set = true;
    }

    const int MROWS = (NN + 127) / 128;                               // 391
    const unsigned spmm_blocks = ((unsigned)EE * 4u + 255u) / 256u;   // 12500

    // zero accumulators
    cudaMemsetAsync(MLPINp, 0, (size_t)5 * NN * 64 * sizeof(float));
    cudaMemsetAsync(Sp, 0, (size_t)NN * 64 * sizeof(float));
    cudaMemsetAsync(DEGp, 0, (size_t)3 * NN * sizeof(float));

    // weight pre-transpose (independent; overlaps with everything)
    transpose_w<<<2, 512>>>(W1, W3, W1Tp, W3Tp);

    // degrees (adj feeds emb's b_dec term; neigh/diff feed sparse_avg)
    deg3_kernel<<<(EE + 255) / 256, 256>>>(adj_src, adj_val, neigh_src, neigh_val, diff_src,
                                           diff_val, DEGp, EE);

    // Xh = half(feat @ W_enc + b_enc)  [NN,64]  (tf32)
    mma_gemm<2><<<dim3(1, MROWS), 256>>>(feat, W_enc, b_enc, nullptr, nullptr, Xhp, NN, 256, 64);

    // h (slot0) + shuf_h (slot2) in one pass; h_g (slot1)
    spmm64h_dual<<<spmm_blocks, 256>>>(adj_src, adj_dst, adj_val, perm, Xhp,
                                       MLPINp + (size_t)0 * NN * 64,
                                       MLPINp + (size_t)2 * NN * 64, EE);
    spmm64h<<<spmm_blocks, 256>>>(gdc_src, gdc_dst, gdc_val, Xhp, MLPINp + (size_t)1 * NN * 64, EE);

    // relu slots 0..2; emit fp16 copies of relu(h), relu(h_g)
    {
        int n4 = 3 * NN * 16;
        relu_emit_half<<<(n4 + 255) / 256, 256>>>((float4*)MLPINp, Hh0p, Hh1p, n4);
    }

    // S = spmm(adj, relu_h); emb = relu(S @ W_dec + deg_adj ⊗ b_dec)  (spmm linearity)
    spmm64h<<<spmm_blocks, 256>>>(adj_src, adj_dst, adj_val, Hh0p, Sp, EE);
    mma_gemm<1><<<dim3(4, MROWS), 256>>>(Sp, W_dec, b_dec, DEGp, emb, nullptr, NN, 64, 256);

    // sparse averages -> sigmoid, slots 3,4
    spmm64h<<<spmm_blocks, 256>>>(neigh_src, neigh_dst, neigh_val, Hh0p,
                                  MLPINp + (size_t)3 * NN * 64, EE);
    spmm64h<<<spmm_blocks, 256>>>(diff_src, diff_dst, diff_val, Hh1p,
                                  MLPINp + (size_t)4 * NN * 64, EE);
    {
        int n2 = 2 * NN * 64;
        sigavg2_kernel<<<(n2 + 255) / 256, 256>>>(MLPINp + (size_t)3 * NN * 64,
                                                  MLPINp + (size_t)4 * NN * 64, DEGp + NN,
                                                  DEGp + 2 * NN);
    }

    // fused batched MLP over all 5 inputs (fp16 tensor cores, pre-transposed weights)
    {
        int M = 5 * NN;
        mlp16<<<(M + 255) / 256, 512, MLP_SMEM>>>(MLPINp, W1Tp, b1, prelu_a, W3Tp, b3, MLPOUTp, M);
    }

    // discriminator heads
    disc_kernel<<<(NN + 3) / 4, 128>>>(MLPOUTp, W_disc, b_disc, ret, ret_a);
}